// round 9
// baseline (speedup 1.0000x reference)
#include <cuda_runtime.h>

// Problem constants
#define LDIM   128
#define RDIM   2048
#define EDIM   32
#define FDIM   64
#define KTOT   2048
#define BATCH  8

// Tiling: CTA tile = 128 L x 256 R x (ECH*FDIM) k, thread tile = 16L x 4R
#define KT       16
#define RT       256
#define ECH      2
#define NSTAGE   ((ECH*FDIM)/KT)     // 8
#define NTHREADS 512
#define AROW     132                 // A tile padded row (words)
#define BROW     260                 // B tile / zb padded row (words)

// rbf(d,e) = exp(-((d-mu_e)/sigma)^2) = 2^(-(KC*(d-mu_e))^2)
#define KC_CONST   3.2029930899845557f
#define MU_STEP    (12.0f/31.0f)

// smem layout (floats):
//   A tiles  [2][KT][AROW]              = 4224   (16896 B)
//   B tiles  [2][KT][BROW]              = 8320   (33280 B)
//   zb       [128][BROW]                = 33280  (133120 B)
#define SM_A   0
#define SM_B   (2*KT*AROW)
#define SM_ZB  (SM_B + 2*KT*BROW)
#define SM_FLOATS (SM_ZB + 128*BROW)
#define SMEM_BYTES (SM_FLOATS * 4)

__device__ __forceinline__ unsigned long long dup2(float x) {
    unsigned long long r;
    unsigned int u = __float_as_uint(x);
    asm("mov.b64 %0, {%1, %1};" : "=l"(r) : "r"(u));
    return r;
}
__device__ __forceinline__ void fma2(unsigned long long &acc,
                                     unsigned long long a,
                                     unsigned long long b) {
    asm("fma.rn.f32x2 %0, %1, %2, %0;" : "+l"(acc) : "l"(a), "l"(b));
}
__device__ __forceinline__ void unpack2(unsigned long long v, float &lo, float &hi) {
    unsigned int a, b;
    asm("mov.b64 {%0, %1}, %2;" : "=r"(a), "=r"(b) : "l"(v));
    lo = __uint_as_float(a);
    hi = __uint_as_float(b);
}
__device__ __forceinline__ float ex2a(float x) {
    float r; asm("ex2.approx.ftz.f32 %0, %1;" : "=f"(r) : "f"(x)); return r;
}
__device__ __forceinline__ float sqrta(float x) {
    float r; asm("sqrt.approx.f32 %0, %1;" : "=f"(r) : "f"(x)); return r;
}

__global__ void ff_init_kernel(float* out) {
    if (threadIdx.x < BATCH) out[threadIdx.x] = 0.0f;
}

__global__ void __launch_bounds__(NTHREADS, 1)
ff_main_kernel(const float* __restrict__ ligf,
               const float* __restrict__ recf,
               const float* __restrict__ ligc,
               const float* __restrict__ recc,
               float* __restrict__ out)
{
    extern __shared__ __align__(16) float smem[];
    float* As = smem + SM_A;
    float* Bs = smem + SM_B;
    float* zb = smem + SM_ZB;

    const int tid  = threadIdx.x;
    const int lane = tid & 31;
    const int w    = tid >> 5;            // 0..15
    const int lg   = w & 7;               // l-group: l0 = lg*16
    const int rh   = w >> 3;              // r-half:  rbase = rh*128
    const int l0    = lg * 16;
    const int rbase = rh * 128;

    const int rt = blockIdx.x;            // 0..7
    const int ec = blockIdx.y;            // 0..15
    const int b  = blockIdx.z;            // 0..7

    const int r0    = rt * RT;
    const int e0    = ec * ECH;
    const int kbase = e0 * FDIM;

    const float* Ag = ligf + (size_t)b * LDIM * KTOT + kbase;
    const float* Bg = recf + (size_t)b * RDIM * KTOT + (size_t)r0 * KTOT + kbase;

    // ---- precompute zb[l][r] = KC * dist(l, r0+r) ----
    // 512 threads: each computes 64 entries: l = tid>>2 half? use l=tid&127, r strided
    {
        const int lz = tid & 127;
        const int rq = tid >> 7;          // 0..3: r block of 64
        const float* p = ligc + ((size_t)b * LDIM + lz) * 3;
        float lx = p[0], ly = p[1], lzc = p[2];
        #pragma unroll
        for (int j = 0; j < 64; j++) {
            const int r = rq * 64 + j;
            const float* q = recc + ((size_t)b * RDIM + r0 + r) * 3;
            float dx = lx - q[0], dy = ly - q[1], dz = lzc - q[2];
            float dd = fmaf(dx, dx, fmaf(dy, dy, dz * dz));
            zb[lz * BROW + r] = KC_CONST * sqrta(dd);
        }
    }

    // acc[p][j]: packed {l = l0+2p, l0+2p+1} x r = rbase+4*lane+j
    unsigned long long acc[8][4];
    #pragma unroll
    for (int p = 0; p < 8; p++)
        #pragma unroll
        for (int j = 0; j < 4; j++)
            acc[p][j] = 0ULL;

    float u_acc = 0.0f;

    // staging assignments
    const int arow = tid >> 2;            // 0..127
    const int acol = (tid & 3) * 4;       // 0,4,8,12
    const int brow = tid >> 1;            // 0..255
    const int bcol = (tid & 1) * 8;       // 0,8

    // ---- prefetch stage 0 ----
    float4 pa, pb0, pb1;
    pa  = *(const float4*)(Ag + (size_t)arow * KTOT + acol);
    pb0 = *(const float4*)(Bg + (size_t)brow * KTOT + bcol);
    pb1 = *(const float4*)(Bg + (size_t)brow * KTOT + bcol + 4);

    #pragma unroll 1
    for (int s = 0; s < NSTAGE; s++) {
        const int buf = s & 1;
        float* Asb = As + buf * (KT * AROW);
        float* Bsb = Bs + buf * (KT * BROW);

        // store staged tile
        {
            float va[4]  = {pa.x, pa.y, pa.z, pa.w};
            float vb[8]  = {pb0.x, pb0.y, pb0.z, pb0.w,
                            pb1.x, pb1.y, pb1.z, pb1.w};
            #pragma unroll
            for (int j = 0; j < 4; j++)
                Asb[(acol + j) * AROW + arow] = va[j];
            #pragma unroll
            for (int j = 0; j < 8; j++)
                Bsb[(bcol + j) * BROW + brow] = vb[j];
        }
        __syncthreads();

        // prefetch next stage
        if (s + 1 < NSTAGE) {
            const int ko = (s + 1) * KT;
            pa  = *(const float4*)(Ag + (size_t)arow * KTOT + ko + acol);
            pb0 = *(const float4*)(Bg + (size_t)brow * KTOT + ko + bcol);
            pb1 = *(const float4*)(Bg + (size_t)brow * KTOT + ko + bcol + 4);
        }

        // ---- main compute: KT k-steps, 16L x 4R per thread ----
        #pragma unroll
        for (int k = 0; k < KT; k++) {
            // A: 8 l-pairs, broadcast within warp (4x LDS.128, 1 wf each)
            unsigned long long a2[8];
            {
                const ulonglong2* Ar = (const ulonglong2*)(Asb + k * AROW + l0);
                ulonglong2 t0 = Ar[0];
                ulonglong2 t1 = Ar[1];
                ulonglong2 t2 = Ar[2];
                ulonglong2 t3 = Ar[3];
                a2[0] = t0.x; a2[1] = t0.y; a2[2] = t1.x; a2[3] = t1.y;
                a2[4] = t2.x; a2[5] = t2.y; a2[6] = t3.x; a2[7] = t3.y;
            }
            // B: 4 consecutive r per lane (1x LDS.128, conflict-free)
            float4 bf = *(const float4*)(Bsb + k * BROW + rbase + 4 * lane);
            unsigned long long b2[4];
            b2[0] = dup2(bf.x);
            b2[1] = dup2(bf.y);
            b2[2] = dup2(bf.z);
            b2[3] = dup2(bf.w);

            #pragma unroll
            for (int p = 0; p < 8; p++)
                #pragma unroll
                for (int j = 0; j < 4; j++)
                    fma2(acc[p][j], a2[p], b2[j]);
        }

        // ---- epilogue fold at each e boundary (every FDIM/KT = 4 stages) ----
        if ((s & 3) == 3) {
            const int e = e0 + (s >> 2);
            const float c2 = KC_CONST * MU_STEP * (float)e;
            #pragma unroll
            for (int p = 0; p < 8; p++) {
                const float4 zv0 = *(const float4*)(zb + (l0 + 2 * p)     * BROW + rbase + 4 * lane);
                const float4 zv1 = *(const float4*)(zb + (l0 + 2 * p + 1) * BROW + rbase + 4 * lane);
                const float z0[4] = {zv0.x, zv0.y, zv0.z, zv0.w};
                const float z1[4] = {zv1.x, zv1.y, zv1.z, zv1.w};
                #pragma unroll
                for (int j = 0; j < 4; j++) {
                    float dot0, dot1;
                    unpack2(acc[p][j], dot0, dot1);
                    float za = z0[j] - c2;
                    float zbv = z1[j] - c2;
                    u_acc = fmaf(ex2a(-za * za),  dot0, u_acc);
                    u_acc = fmaf(ex2a(-zbv * zbv), dot1, u_acc);
                    acc[p][j] = 0ULL;
                }
            }
        }
    }

    // ---- block reduction + atomic accumulate into U[b] ----
    #pragma unroll
    for (int o = 16; o > 0; o >>= 1)
        u_acc += __shfl_xor_sync(0xffffffffu, u_acc, o);

    __syncthreads();                       // tiles done; reuse as scratch
    float* red = smem;
    if (lane == 0) red[w] = u_acc;
    __syncthreads();
    if (tid == 0) {
        float ssum = 0.0f;
        #pragma unroll
        for (int ww = 0; ww < NTHREADS / 32; ww++) ssum += red[ww];
        atomicAdd(out + b, ssum * 0.01f);  // ENERGY_SCALE
    }
}

extern "C" void kernel_launch(void* const* d_in, const int* in_sizes, int n_in,
                              void* d_out, int out_size) {
    (void)in_sizes; (void)n_in; (void)out_size;
    const float* lig_feat  = (const float*)d_in[0];
    const float* rec_feat  = (const float*)d_in[1];
    const float* lig_coord = (const float*)d_in[2];
    const float* rec_coord = (const float*)d_in[3];
    float* out = (float*)d_out;

    cudaFuncSetAttribute(ff_main_kernel,
                         cudaFuncAttributeMaxDynamicSharedMemorySize,
                         SMEM_BYTES);

    ff_init_kernel<<<1, 32>>>(out);

    dim3 grid(RDIM / RT, EDIM / ECH, BATCH);   // (8, 16, 8) = 1024 CTAs
    ff_main_kernel<<<grid, NTHREADS, SMEM_BYTES>>>(lig_feat, rec_feat,
                                                   lig_coord, rec_coord, out);
}

// round 10
// speedup vs baseline: 1.6035x; 1.6035x over previous
#include <cuda_runtime.h>

// Problem constants
#define LDIM   128
#define RDIM   2048
#define EDIM   32
#define FDIM   64
#define KTOT   2048
#define BATCH  8

// Tiling: CTA tile = 64 L x 128 R x (ECH*FDIM) k, thread tile = 8L x 4R
// 256 threads/CTA, 2 CTAs per SM (reg ceiling 128, smem 25.6KB/CTA)
#define KT       16
#define RT       128
#define LT       64
#define ECH      4
#define NSTAGE   ((ECH*FDIM)/KT)     // 16
#define NTHREADS 256
#define AROW     68                  // A tile padded row (words)
#define BROW     132                 // B tile padded row (words)

// rbf(d,e) = exp(-((d-mu_e)/sigma)^2) = 2^(-(KC*(d-mu_e))^2)
#define KC_CONST   3.2029930899845557f
#define MU_STEP    (12.0f/31.0f)

__device__ __forceinline__ unsigned long long dup2(float x) {
    unsigned long long r;
    unsigned int u = __float_as_uint(x);
    asm("mov.b64 %0, {%1, %1};" : "=l"(r) : "r"(u));
    return r;
}
__device__ __forceinline__ void fma2(unsigned long long &acc,
                                     unsigned long long a,
                                     unsigned long long b) {
    asm("fma.rn.f32x2 %0, %1, %2, %0;" : "+l"(acc) : "l"(a), "l"(b));
}
__device__ __forceinline__ void unpack2(unsigned long long v, float &lo, float &hi) {
    unsigned int a, b;
    asm("mov.b64 {%0, %1}, %2;" : "=r"(a), "=r"(b) : "l"(v));
    lo = __uint_as_float(a);
    hi = __uint_as_float(b);
}
__device__ __forceinline__ float ex2a(float x) {
    float r; asm("ex2.approx.ftz.f32 %0, %1;" : "=f"(r) : "f"(x)); return r;
}
__device__ __forceinline__ float sqrta(float x) {
    float r; asm("sqrt.approx.f32 %0, %1;" : "=f"(r) : "f"(x)); return r;
}

__global__ void ff_init_kernel(float* out) {
    if (threadIdx.x < BATCH) out[threadIdx.x] = 0.0f;
}

__global__ void __launch_bounds__(NTHREADS, 2)
ff_main_kernel(const float* __restrict__ ligf,
               const float* __restrict__ recf,
               const float* __restrict__ ligc,
               const float* __restrict__ recc,
               float* __restrict__ out)
{
    // A tile [2][KT][AROW] + B tile [2][KT][BROW]  (25.6 KB)
    __shared__ __align__(16) float smem[2 * KT * AROW + 2 * KT * BROW];
    float* As = smem;
    float* Bs = smem + 2 * KT * AROW;

    const int tid  = threadIdx.x;
    const int lane = tid & 31;         // owns r = 4*lane .. 4*lane+3
    const int w    = tid >> 5;         // warp id 0..7; owns l = w*8 .. w*8+7

    const int rt = blockIdx.x;         // 0..15
    const int yc = blockIdx.y;         // 0..15 : lh = yc>>3, ec = yc&7
    const int b  = blockIdx.z;         // 0..7
    const int lh = yc >> 3;            // L half (0/1)
    const int ec = yc & 7;             // e chunk

    const int r0    = rt * RT;
    const int l0g   = lh * LT;         // CTA's global L base
    const int e0    = ec * ECH;
    const int kbase = e0 * FDIM;

    const float* Ag = ligf + ((size_t)b * LDIM + l0g) * KTOT + kbase;
    const float* Bg = recf + ((size_t)b * RDIM + r0) * KTOT + kbase;

    // staging: A 64x16 = 1 float4/thread, B 128x16 = 2 float4/thread
    const int arow = tid >> 2;          // 0..63
    const int acol = (tid & 3) * 4;     // 0,4,8,12
    const int brow = tid >> 1;          // 0..127
    const int bcol = (tid & 1) * 8;     // 0,8

    // ---- distances for this thread's 8x4 pairs (registers) ----
    float dist[8][4];
    {
        float lx[8], ly[8], lz[8];
        #pragma unroll
        for (int i = 0; i < 8; i++) {
            const float* p = ligc + ((size_t)b * LDIM + l0g + w * 8 + i) * 3;
            lx[i] = p[0]; ly[i] = p[1]; lz[i] = p[2];
        }
        #pragma unroll
        for (int j = 0; j < 4; j++) {
            const float* p = recc + ((size_t)b * RDIM + r0 + 4 * lane + j) * 3;
            float rx = p[0], ry = p[1], rz = p[2];
            #pragma unroll
            for (int i = 0; i < 8; i++) {
                float dx = lx[i] - rx, dy = ly[i] - ry, dz = lz[i] - rz;
                float dd = fmaf(dx, dx, fmaf(dy, dy, dz * dz));
                dist[i][j] = sqrta(dd);
            }
        }
    }

    // acc[p][j] = packed {l = w*8+2p, w*8+2p+1} x r = 4*lane+j
    unsigned long long acc[4][4];
    #pragma unroll
    for (int p = 0; p < 4; p++)
        #pragma unroll
        for (int j = 0; j < 4; j++)
            acc[p][j] = 0ULL;

    float u_acc = 0.0f;

    // ---- prefetch stage 0 into registers ----
    float4 pa, pb0, pb1;
    pa  = *(const float4*)(Ag + (size_t)arow * KTOT + acol);
    pb0 = *(const float4*)(Bg + (size_t)brow * KTOT + bcol);
    pb1 = *(const float4*)(Bg + (size_t)brow * KTOT + bcol + 4);

    #pragma unroll 1
    for (int s = 0; s < NSTAGE; s++) {
        const int buf = s & 1;
        float* Asb = As + buf * (KT * AROW);
        float* Bsb = Bs + buf * (KT * BROW);

        // store staged tile
        {
            float va[4] = {pa.x, pa.y, pa.z, pa.w};
            float vb[8] = {pb0.x, pb0.y, pb0.z, pb0.w,
                           pb1.x, pb1.y, pb1.z, pb1.w};
            #pragma unroll
            for (int j = 0; j < 4; j++)
                Asb[(acol + j) * AROW + arow] = va[j];
            #pragma unroll
            for (int j = 0; j < 8; j++)
                Bsb[(bcol + j) * BROW + brow] = vb[j];
        }
        __syncthreads();

        // prefetch next stage (latency hidden under compute)
        if (s + 1 < NSTAGE) {
            const int ko = (s + 1) * KT;
            pa  = *(const float4*)(Ag + (size_t)arow * KTOT + ko + acol);
            pb0 = *(const float4*)(Bg + (size_t)brow * KTOT + ko + bcol);
            pb1 = *(const float4*)(Bg + (size_t)brow * KTOT + ko + bcol + 4);
        }

        // ---- main compute: KT k-steps, 8L x 4R per thread ----
        #pragma unroll
        for (int k = 0; k < KT; k++) {
            // A: 4 l-pairs, broadcast within warp (2x LDS.128, 1 wf each)
            unsigned long long a2[4];
            {
                const ulonglong2* Ar = (const ulonglong2*)(Asb + k * AROW + w * 8);
                ulonglong2 t0 = Ar[0];
                ulonglong2 t1 = Ar[1];
                a2[0] = t0.x; a2[1] = t0.y; a2[2] = t1.x; a2[3] = t1.y;
            }
            // B: 4 consecutive r per lane (1x LDS.128, conflict-free)
            float4 bf = *(const float4*)(Bsb + k * BROW + 4 * lane);
            unsigned long long b2[4];
            b2[0] = dup2(bf.x);
            b2[1] = dup2(bf.y);
            b2[2] = dup2(bf.z);
            b2[3] = dup2(bf.w);

            #pragma unroll
            for (int p = 0; p < 4; p++)
                #pragma unroll
                for (int j = 0; j < 4; j++)
                    fma2(acc[p][j], a2[p], b2[j]);
        }

        // ---- epilogue fold at each e boundary (every FDIM/KT = 4 stages) ----
        if ((s & 3) == 3) {
            const int e = e0 + (s >> 2);
            const float c2 = KC_CONST * MU_STEP * (float)e;
            #pragma unroll
            for (int p = 0; p < 4; p++) {
                #pragma unroll
                for (int j = 0; j < 4; j++) {
                    float dot0, dot1;
                    unpack2(acc[p][j], dot0, dot1);
                    float z0 = fmaf(dist[2 * p][j],     KC_CONST, -c2);
                    float z1 = fmaf(dist[2 * p + 1][j], KC_CONST, -c2);
                    u_acc = fmaf(ex2a(-z0 * z0), dot0, u_acc);
                    u_acc = fmaf(ex2a(-z1 * z1), dot1, u_acc);
                    acc[p][j] = 0ULL;
                }
            }
        }
    }

    // ---- block reduction + atomic accumulate into U[b] ----
    #pragma unroll
    for (int o = 16; o > 0; o >>= 1)
        u_acc += __shfl_xor_sync(0xffffffffu, u_acc, o);

    __syncthreads();                       // tiles done; reuse as scratch
    float* red = smem;
    if (lane == 0) red[w] = u_acc;
    __syncthreads();
    if (tid == 0) {
        float ssum = 0.0f;
        #pragma unroll
        for (int ww = 0; ww < NTHREADS / 32; ww++) ssum += red[ww];
        atomicAdd(out + b, ssum * 0.01f);  // ENERGY_SCALE
    }
}

extern "C" void kernel_launch(void* const* d_in, const int* in_sizes, int n_in,
                              void* d_out, int out_size) {
    (void)in_sizes; (void)n_in; (void)out_size;
    const float* lig_feat  = (const float*)d_in[0];
    const float* rec_feat  = (const float*)d_in[1];
    const float* lig_coord = (const float*)d_in[2];
    const float* rec_coord = (const float*)d_in[3];
    float* out = (float*)d_out;

    ff_init_kernel<<<1, 32>>>(out);

    // (16, 16, 8) = 2048 CTAs; 2 CTAs per SM
    dim3 grid(RDIM / RT, (LDIM / LT) * (EDIM / ECH), BATCH);
    ff_main_kernel<<<grid, NTHREADS>>>(lig_feat, rec_feat,
                                       lig_coord, rec_coord, out);
}